// round 15
// baseline (speedup 1.0000x reference)
#include <cuda_runtime.h>
#include <cuda_bf16.h>
#include <math.h>
#include <stdint.h>

#define TT 64
#define BB 2048
#define OBS 48
#define HH 256
#define G4 1024
#define KC 304
#define M1 512
#define M2 256
#define TB (TT*BB)
#define LOG2PI 1.8378770664093453f

typedef __nv_bfloat16 bf16;

// ---------------- scratch ----------------
__device__ __align__(16) bf16 g_Wc[G4 * KC];
__device__ float            g_bias[G4];
__device__ __align__(16) bf16 g_W1b[M1 * HH];
__device__ __align__(16) bf16 g_W2b[M2 * M1];
__device__ __align__(16) bf16 g_Whd[32 * M2];        // [Wm|Ws|0] head weights, [o][k]
__device__ __align__(16) bf16 g_xb[(size_t)TB * OBS];
__device__ __align__(16) bf16 g_hb[(size_t)TB * HH];
__device__ __align__(16) bf16 g_y1[(size_t)TB * M1];

// ---------------- helpers ----------------
__device__ __forceinline__ uint32_t bf2_as_u32(__nv_bfloat162 v) {
    return *reinterpret_cast<uint32_t*>(&v);
}

__device__ __forceinline__ void mma16816(float c[4],
    uint32_t a0, uint32_t a1, uint32_t a2, uint32_t a3,
    uint32_t b0, uint32_t b1)
{
    asm volatile(
        "mma.sync.aligned.m16n8k16.row.col.f32.bf16.bf16.f32 "
        "{%0,%1,%2,%3}, {%4,%5,%6,%7}, {%8,%9}, {%0,%1,%2,%3};"
        : "+f"(c[0]), "+f"(c[1]), "+f"(c[2]), "+f"(c[3])
        : "r"(a0), "r"(a1), "r"(a2), "r"(a3), "r"(b0), "r"(b1));
}

__device__ __forceinline__ void ldsm4(uint32_t& r0, uint32_t& r1,
                                      uint32_t& r2, uint32_t& r3, uint32_t addr)
{
    asm volatile("ldmatrix.sync.aligned.m8n8.x4.shared.b16 {%0,%1,%2,%3}, [%4];"
                 : "=r"(r0), "=r"(r1), "=r"(r2), "=r"(r3) : "r"(addr));
}

__device__ __forceinline__ uint32_t smem_u32(const void* p) {
    uint32_t a;
    asm("{ .reg .u64 t; cvta.to.shared.u64 t, %1; cvt.u32.u64 %0, t; }"
        : "=r"(a) : "l"(p));
    return a;
}

// accurate-ish (MUFU-based, ~2 ulp) nonlinearities for the LSTM recurrence
__device__ __forceinline__ float sig_acc(float x) {
    return __fdividef(1.0f, 1.0f + __expf(-x));
}
__device__ __forceinline__ float tanh_acc(float x) {
    float xc = fminf(fmaxf(x, -15.0f), 15.0f);
    float e = __expf(2.0f * xc);
    return __fdividef(e - 1.0f, e + 1.0f);
}

// ---------------- merged prep kernel ----------------
#define XSEG   ((TB * OBS) / 4)
#define WCSEG  (G4 * KC)
#define W12SEG (M1 * HH + M2 * M1)
#define WHDSEG (32 * M2)
#define PREP_TOTAL (XSEG + WCSEG + W12SEG + WHDSEG)

__global__ void prep_all(
    const float* __restrict__ x,
    const float* __restrict__ W_hh, const float* __restrict__ W_ih,
    const float* __restrict__ b_ih, const float* __restrict__ b_hh,
    const float* __restrict__ W1, const float* __restrict__ W2,
    const float* __restrict__ Wm, const float* __restrict__ Ws)
{
    int idx = blockIdx.x * blockDim.x + threadIdx.x;
    if (idx < XSEG) {
        float4 v = *(const float4*)(x + (size_t)idx * 4);
        uint2 p;
        p.x = bf2_as_u32(__floats2bfloat162_rn(v.x, v.y));
        p.y = bf2_as_u32(__floats2bfloat162_rn(v.z, v.w));
        *(uint2*)(g_xb + (size_t)idx * 4) = p;
        return;
    }
    idx -= XSEG;
    if (idx < WCSEG) {
        int n = idx / KC, k = idx % KC;
        int g = n & 3, j = n >> 2;
        float v = (k < HH) ? W_hh[(size_t)(g * HH + j) * HH + k]
                           : W_ih[(size_t)(g * HH + j) * OBS + (k - HH)];
        g_Wc[idx] = __float2bfloat16(v);
        if (k == 0) g_bias[n] = b_ih[g * HH + j] + b_hh[g * HH + j];
        return;
    }
    idx -= WCSEG;
    if (idx < W12SEG) {
        if (idx < M1 * HH) {
            int n = idx / HH, k = idx % HH;
            g_W1b[idx] = __float2bfloat16(W1[(size_t)k * M1 + n]);
        } else {
            int i = idx - M1 * HH;
            int n = i / M1, k = i % M1;
            g_W2b[i] = __float2bfloat16(W2[(size_t)k * M2 + n]);
        }
        return;
    }
    idx -= W12SEG;
    if (idx < WHDSEG) {
        int o = idx / M2, k = idx % M2;
        float v = 0.0f;
        if (o < 12) v = Wm[k * 12 + o];
        else if (o < 24) v = Ws[k * 12 + (o - 12)];
        g_Whd[idx] = __float2bfloat16(v);
    }
}

// ---------------- persistent cluster LSTM (accurate gates) ----------------
#define SM_BIAS  0
#define SM_A     1024
#define SM_STAGE 43008
#define SM_B     52224
#define SM_TOTAL 220160
#define ASTR_B 656
#define STG_B  144

__global__ void __launch_bounds__(256, 1) __cluster_dims__(4, 1, 1)
lstm_persist(const float* __restrict__ h0, const float* __restrict__ c0,
             const int* __restrict__ done)
{
    extern __shared__ char smx[];
    const uint32_t smb = smem_u32(smx);

    const int tid = threadIdx.x;
    const int lane = tid & 31, warp = tid >> 5;
    const int wm = warp & 1, wn = warp >> 1;
    const int g8 = lane >> 2, t4 = lane & 3;

    uint32_t rank;
    asm("mov.u32 %0, %%cluster_ctarank;" : "=r"(rank));
    const int b0 = (blockIdx.x >> 2) * 64;
    const int jbase = rank * 64;

    float* bias_s = (float*)(smx + SM_BIAS);
    bias_s[tid] = g_bias[rank * 256 + tid];

    for (int u = tid; u < 256 * 38; u += 256) {
        int n = u / 38, off = u % 38;
        uint4 v = *(const uint4*)((const char*)g_Wc + (size_t)(rank * 256 + n) * 608 + off * 16);
        *(uint4*)(smx + SM_B + n * ASTR_B + off * 16) = v;
    }
    for (int u = tid; u < 4096; u += 256) {
        int row = u >> 6, c4 = u & 63;
        float4 v = *(const float4*)(h0 + (size_t)(b0 + row) * HH + c4 * 4);
        uint2 p;
        p.x = bf2_as_u32(__floats2bfloat162_rn(v.x, v.y));
        p.y = bf2_as_u32(__floats2bfloat162_rn(v.z, v.w));
        *(uint2*)(smx + SM_A + row * ASTR_B + c4 * 8) = p;
    }
    {
        const uint4* xs = (const uint4*)(g_xb + (size_t)b0 * OBS);
        for (int u = tid; u < 384; u += 256) {
            uint4 v = xs[u];
            int e = u * 8, row = e / 48, col = e % 48;
            *(uint4*)(smx + SM_A + row * ASTR_B + 512 + col * 2) = v;
        }
    }
    float creg[16];
#pragma unroll
    for (int am = 0; am < 2; am++)
#pragma unroll
        for (int an = 0; an < 8; an++) {
            int r = wm * 32 + am * 16 + g8 + (t4 & 1) * 8;
            int jl = wn * 16 + an * 2 + (t4 >> 1);
            creg[am * 8 + an] = c0[(size_t)(b0 + r) * HH + jbase + jl];
        }
    __syncthreads();

    const int mi = lane >> 3;
    const int rowoff = ((mi & 1) << 3) + (lane & 7);
    const uint32_t kboff = (uint32_t)((mi >> 1) << 4);
    uint32_t aBase[2], bBase[4];
#pragma unroll
    for (int am = 0; am < 2; am++)
        aBase[am] = smb + SM_A + (wm * 32 + am * 16 + rowoff) * ASTR_B + kboff;
#pragma unroll
    for (int p = 0; p < 4; p++)
        bBase[p] = smb + SM_B + (wn * 64 + p * 16 + rowoff) * ASTR_B + kboff;

    uint32_t peerA[4];
#pragma unroll
    for (int r = 0; r < 4; r++) {
        uint32_t a;
        asm("mapa.shared::cluster.u32 %0, %1, %2;" : "=r"(a) : "r"(smb + SM_A), "r"(r));
        peerA[r] = a;
    }

    const int base_r = wm * 32 + g8;
    int d0, d1, d2, d3;
    {
        const int* dt = done + b0;
        d0 = dt[base_r]; d1 = dt[base_r + 8];
        d2 = dt[base_r + 16]; d3 = dt[base_r + 24];
    }

#pragma unroll 1
    for (int t = 0; t < TT; t++) {
        uint32_t m0 = d0 ? 0u : ~0u, m1 = d1 ? 0u : ~0u;
        uint32_t m2 = d2 ? 0u : ~0u, m3 = d3 ? 0u : ~0u;

        float acc[2][8][4];
#pragma unroll
        for (int i = 0; i < 2; i++)
#pragma unroll
            for (int j = 0; j < 8; j++)
#pragma unroll
                for (int k = 0; k < 4; k++) acc[i][j][k] = 0.0f;

        if (t)
            asm volatile("barrier.cluster.wait.aligned;" ::: "memory");

#pragma unroll
        for (int ch = 0; ch < 19; ch++) {
            uint32_t a[2][4];
            ldsm4(a[0][0], a[0][1], a[0][2], a[0][3], aBase[0] + ch * 32);
            ldsm4(a[1][0], a[1][1], a[1][2], a[1][3], aBase[1] + ch * 32);
            if (ch < 16) {
                a[0][0] &= m0; a[0][2] &= m0; a[0][1] &= m1; a[0][3] &= m1;
                a[1][0] &= m2; a[1][2] &= m2; a[1][1] &= m3; a[1][3] &= m3;
            }
#pragma unroll
            for (int p = 0; p < 4; p++) {
                uint32_t br0, br1, br2, br3;
                ldsm4(br0, br1, br2, br3, bBase[p] + ch * 32);
#pragma unroll
                for (int am = 0; am < 2; am++) {
                    mma16816(acc[am][2 * p],     a[am][0], a[am][1], a[am][2], a[am][3], br0, br2);
                    mma16816(acc[am][2 * p + 1], a[am][0], a[am][1], a[am][2], a[am][3], br1, br3);
                }
            }
        }

        asm volatile("barrier.cluster.arrive.aligned;" ::: "memory");   // B1 arrive

        uint4 xr0, xr1;
        int dn0 = 0, dn1 = 0, dn2 = 0, dn3 = 0;
        const bool hx = (t < TT - 1);
        if (hx) {
            const uint4* xs = (const uint4*)(g_xb + ((size_t)(t + 1) * BB + b0) * OBS);
            xr0 = xs[tid];
            if (tid < 128) xr1 = xs[tid + 256];
            const int* dt = done + (size_t)(t + 1) * BB + b0;
            dn0 = dt[base_r]; dn1 = dt[base_r + 8];
            dn2 = dt[base_r + 16]; dn3 = dt[base_r + 24];
        }

        const bool odd = (t4 & 1);
#pragma unroll
        for (int am = 0; am < 2; am++) {
            const int dlo = (am == 0) ? d0 : d2;
            const int dhi = (am == 0) ? d1 : d3;
            const int dflag = odd ? dhi : dlo;
#pragma unroll
            for (int an = 0; an < 8; an++) {
                float* a = acc[am][an];
                float s0 = odd ? a[0] : a[2];
                float s1 = odd ? a[1] : a[3];
                float e0 = __shfl_xor_sync(0xffffffffu, s0, 1);
                float e1 = __shfl_xor_sync(0xffffffffu, s1, 1);
                float q0 = odd ? e0 : a[0];
                float q1 = odd ? e1 : a[1];
                float q2 = odd ? a[2] : e0;
                float q3 = odd ? a[3] : e1;
                int jl = wn * 16 + an * 2 + (t4 >> 1);
                float4 bb = *(const float4*)&bias_s[jl * 4];
                float gi = q0 + bb.x, gf = q1 + bb.y, gg = q2 + bb.z, go = q3 + bb.w;
                int cell = am * 8 + an;
                float cold = dflag ? 0.0f : creg[cell];
                float cn = sig_acc(gf) * cold + sig_acc(gi) * tanh_acc(gg);
                creg[cell] = cn;
                float hn = sig_acc(go) * tanh_acc(cn);
                int r = wm * 32 + am * 16 + g8 + (odd ? 8 : 0);
                *(bf16*)(smx + SM_STAGE + r * STG_B + jl * 2) = __float2bfloat16(hn);
            }
        }

        if (hx) {
            int e = tid * 8;
            *(uint4*)(smx + SM_A + (e / 48) * ASTR_B + 512 + (e % 48) * 2) = xr0;
            if (tid < 128) {
                int e2 = (tid + 256) * 8;
                *(uint4*)(smx + SM_A + (e2 / 48) * ASTR_B + 512 + (e2 % 48) * 2) = xr1;
            }
        }

        __syncthreads();
        asm volatile("barrier.cluster.wait.aligned;" ::: "memory");     // B1 wait

#pragma unroll
        for (int q = 0; q < 2; q++) {
            int u = tid + q * 256;
            int row = u >> 3, off = u & 7;
            uint4 v = *(const uint4*)(smx + SM_STAGE + row * STG_B + off * 16);
#pragma unroll
            for (int r = 0; r < 4; r++) {
                uint32_t da = peerA[r] + row * ASTR_B + jbase * 2 + off * 16;
                asm volatile("st.shared::cluster.v4.b32 [%0], {%1,%2,%3,%4};"
                             :: "r"(da), "r"(v.x), "r"(v.y), "r"(v.z), "r"(v.w) : "memory");
            }
            *(uint4*)(g_hb + ((size_t)t * BB + b0 + row) * HH + jbase + off * 8) = v;
        }

        asm volatile("barrier.cluster.arrive.aligned;" ::: "memory");   // B2 arrive
        d0 = dn0; d1 = dn1; d2 = dn2; d3 = dn3;
    }
    asm volatile("barrier.cluster.wait.aligned;" ::: "memory");
}

// ---------------- A-hot GEMM; double-buffered B; NWARP-parameterized ----------------
template <int KD, int NT, bool LNA, bool HEADS, int NWARP>
__global__ __launch_bounds__(NWARP * 32) void gemm_hot(
    const bf16* __restrict__ A, const bf16* __restrict__ Bw,
    const float* __restrict__ bias, bf16* __restrict__ Out,
    const float* __restrict__ gamma, const float* __restrict__ beta,
    const float* __restrict__ bm, const float* __restrict__ bsv,
    float* __restrict__ outF)
{
    constexpr int THREADS = NWARP * 32;
    constexpr int AST = KD + 8;
    constexpr int ASZ = 64 * AST * 2;
    constexpr int NW2 = NWARP / 2;           // n-warps
    constexpr int NPW = NT / NW2;            // N cols per warp
    constexpr int PG  = NPW / 16;            // B ldsm groups per warp
    constexpr int AN  = NPW / 8;             // n-atoms per warp
    constexpr int CH  = KD / 32;
    constexpr int BLD = (NT * 4) / THREADS;  // uint4 B transfers per thread per chunk
    constexpr int BUFB = NT * 80;

    extern __shared__ char sm[];
    char* smA  = sm;
    char* smB0 = sm + ASZ;
    char* smB1 = sm + ASZ + BUFB;
    char* smW  = smB0;                       // HEADS: reuse B region post-loop

    const int tid = threadIdx.x;
    const int lane = tid & 31, warp = tid >> 5;
    const int wm = warp & 1, wn = warp >> 1;
    const int g8 = lane >> 2, t4 = lane & 3;
    const size_t m0 = (size_t)blockIdx.x * 64;
    const int n0 = blockIdx.y * NT;

    // ---- load A tile (once); LN in-kernel if LNA ----
    if (LNA) {
#pragma unroll
        for (int it = 0; it < 64 * (KD / 8) / THREADS; it++) {
            int u = tid + it * THREADS;
            int row = u >> 5, pos = u & 31;
            uint4 v = *(const uint4*)(A + (m0 + row) * KD + pos * 8);
            __nv_bfloat162* vp = (__nv_bfloat162*)&v;
            float f[8];
#pragma unroll
            for (int q = 0; q < 4; q++) {
                float2 t2 = __bfloat1622float2(vp[q]);
                f[2 * q] = t2.x; f[2 * q + 1] = t2.y;
            }
            float s = 0.0f, s2 = 0.0f;
#pragma unroll
            for (int q = 0; q < 8; q++) { s += f[q]; s2 += f[q] * f[q]; }
#pragma unroll
            for (int o = 16; o; o >>= 1) {
                s  += __shfl_xor_sync(0xffffffffu, s, o);
                s2 += __shfl_xor_sync(0xffffffffu, s2, o);
            }
            float mu = s * (1.0f / HH);
            float rs = rsqrtf(s2 * (1.0f / HH) - mu * mu + 1e-5f);
#pragma unroll
            for (int q = 0; q < 8; q++) {
                int c = pos * 8 + q;
                f[q] = (f[q] - mu) * rs * __ldg(&gamma[c]) + __ldg(&beta[c]);
            }
#pragma unroll
            for (int q = 0; q < 4; q++)
                vp[q] = __floats2bfloat162_rn(f[2 * q], f[2 * q + 1]);
            *(uint4*)(smA + row * AST * 2 + pos * 16) = v;
        }
    } else {
        for (int u = tid; u < 64 * (KD / 8); u += THREADS) {
            int row = u / (KD / 8), pos = u % (KD / 8);
            uint4 v = *(const uint4*)(A + (m0 + row) * KD + pos * 8);
            *(uint4*)(smA + row * AST * 2 + pos * 16) = v;
        }
    }

    uint4 breg[BLD];
#pragma unroll
    for (int i = 0; i < BLD; i++) {
        int u = tid + i * THREADS;
        int row = u >> 2, q = u & 3;
        breg[i] = *(const uint4*)(Bw + (size_t)(n0 + row) * KD + q * 8);
    }

    float acc[2][AN][4];
#pragma unroll
    for (int i = 0; i < 2; i++)
#pragma unroll
        for (int j = 0; j < AN; j++)
#pragma unroll
            for (int k = 0; k < 4; k++) acc[i][j][k] = 0.0f;

    const int mi = lane >> 3;
    const int rowoff = ((mi & 1) << 3) + (lane & 7);
    const uint32_t kb16 = (uint32_t)((mi >> 1) << 4);
    const uint32_t smAu = smem_u32(smA);
    const uint32_t smB0u = smem_u32(smB0);
    uint32_t aB[2], bB[PG];
#pragma unroll
    for (int am = 0; am < 2; am++)
        aB[am] = smAu + (wm * 32 + am * 16 + rowoff) * (AST * 2) + kb16;
#pragma unroll
    for (int p = 0; p < PG; p++)
        bB[p] = smB0u + (wn * NPW + p * 16 + rowoff) * 80 + kb16;

    // ---- K loop: one sync per chunk, double-buffered B ----
#pragma unroll 1
    for (int c = 0; c < CH; c++) {
        const uint32_t bufOff = (c & 1) ? (uint32_t)BUFB : 0u;
        char* bufc = (c & 1) ? smB1 : smB0;
#pragma unroll
        for (int i = 0; i < BLD; i++) {
            int u = tid + i * THREADS;
            int row = u >> 2, q = u & 3;
            *(uint4*)(bufc + row * 80 + q * 16) = breg[i];
        }
        __syncthreads();
        if (c + 1 < CH) {
#pragma unroll
            for (int i = 0; i < BLD; i++) {
                int u = tid + i * THREADS;
                int row = u >> 2, q = u & 3;
                breg[i] = *(const uint4*)(Bw + (size_t)(n0 + row) * KD + (c + 1) * 32 + q * 8);
            }
        }
#pragma unroll
        for (int ks = 0; ks < 2; ks++) {
            int s = c * 2 + ks;
            uint32_t a[2][4];
            ldsm4(a[0][0], a[0][1], a[0][2], a[0][3], aB[0] + s * 32);
            ldsm4(a[1][0], a[1][1], a[1][2], a[1][3], aB[1] + s * 32);
#pragma unroll
            for (int p = 0; p < PG; p++) {
                uint32_t br0, br1, br2, br3;
                ldsm4(br0, br1, br2, br3, bB[p] + bufOff + ks * 32);
#pragma unroll
                for (int am = 0; am < 2; am++) {
                    mma16816(acc[am][2 * p],     a[am][0], a[am][1], a[am][2], a[am][3], br0, br2);
                    mma16816(acc[am][2 * p + 1], a[am][0], a[am][1], a[am][2], a[am][3], br1, br3);
                }
            }
        }
    }

    if (!HEADS) {
#pragma unroll
        for (int am = 0; am < 2; am++)
#pragma unroll
            for (int an = 0; an < AN; an++) {
                size_t r = m0 + wm * 32 + am * 16 + g8;
                int c = n0 + wn * NPW + an * 8 + t4 * 2;
                float bc0 = __ldg(&bias[c]), bc1 = __ldg(&bias[c + 1]);
                float v0 = acc[am][an][0] + bc0;
                float v1 = acc[am][an][1] + bc1;
                v0 = (v0 > 0.0f) ? v0 : expm1f(v0);
                v1 = (v1 > 0.0f) ? v1 : expm1f(v1);
                *(__nv_bfloat162*)(Out + r * (M1) + c) = __floats2bfloat162_rn(v0, v1);
                float v2 = acc[am][an][2] + bc0;
                float v3 = acc[am][an][3] + bc1;
                v2 = (v2 > 0.0f) ? v2 : expm1f(v2);
                v3 = (v3 > 0.0f) ? v3 : expm1f(v3);
                *(__nv_bfloat162*)(Out + (r + 8) * (M1) + c) = __floats2bfloat162_rn(v2, v3);
            }
    } else {
        // ---- tensor-core heads epilogue ----
        __syncthreads();
        char* ys = smA;
        for (int u = tid; u < 1024; u += THREADS) {
            int row = u >> 5, q = u & 31;
            *(uint4*)(smW + row * 528 + q * 16) = *(const uint4*)(g_Whd + row * M2 + q * 8);
        }
#pragma unroll
        for (int am = 0; am < 2; am++)
#pragma unroll
            for (int an = 0; an < AN; an++) {
                int r = wm * 32 + am * 16 + g8;
                int c = wn * NPW + an * 8 + t4 * 2;
                float bc0 = __ldg(&bias[c]), bc1 = __ldg(&bias[c + 1]);
                float v0 = acc[am][an][0] + bc0;
                float v1 = acc[am][an][1] + bc1;
                v0 = (v0 > 0.0f) ? v0 : expm1f(v0);
                v1 = (v1 > 0.0f) ? v1 : expm1f(v1);
                *(__nv_bfloat162*)(ys + r * 528 + c * 2) = __floats2bfloat162_rn(v0, v1);
                float v2 = acc[am][an][2] + bc0;
                float v3 = acc[am][an][3] + bc1;
                v2 = (v2 > 0.0f) ? v2 : expm1f(v2);
                v3 = (v3 > 0.0f) ? v3 : expm1f(v3);
                *(__nv_bfloat162*)(ys + (r + 8) * 528 + c * 2) = __floats2bfloat162_rn(v2, v3);
            }
        __syncthreads();

        if (warp < 4) {
            const uint32_t aH = smem_u32(ys) + (warp * 16 + rowoff) * 528 + kb16;
            const uint32_t smWu = smem_u32(smW);
            const uint32_t bH0 = smWu + rowoff * 528 + kb16;
            const uint32_t bH1 = smWu + (16 + rowoff) * 528 + kb16;

            float ah[4][4];
#pragma unroll
            for (int i = 0; i < 4; i++)
#pragma unroll
                for (int k = 0; k < 4; k++) ah[i][k] = 0.0f;

#pragma unroll
            for (int s = 0; s < 16; s++) {
                uint32_t a0, a1, a2, a3;
                ldsm4(a0, a1, a2, a3, aH + s * 32);
                uint32_t b0, b1, b2, b3;
                ldsm4(b0, b1, b2, b3, bH0 + s * 32);
                mma16816(ah[0], a0, a1, a2, a3, b0, b2);
                mma16816(ah[1], a0, a1, a2, a3, b1, b3);
                ldsm4(b0, b1, b2, b3, bH1 + s * 32);
                mma16816(ah[2], a0, a1, a2, a3, b0, b2);
                mma16816(ah[3], a0, a1, a2, a3, b1, b3);
            }

            int r = warp * 16 + g8;
            float Slo = 0.0f, Shi = 0.0f;
#pragma unroll
            for (int an = 0; an < 4; an++)
#pragma unroll
                for (int j = 0; j < 2; j++) {
                    int o = an * 8 + t4 * 2 + j;
                    float vlo = ah[an][j], vhi = ah[an][2 + j];
                    if (o < 12) {
                        float bb = __ldg(&bm[o]);
                        outF[(m0 + r) * 14 + o]     = vlo + bb;
                        outF[(m0 + r + 8) * 14 + o] = vhi + bb;
                    } else if (o < 24) {
                        float bb = __ldg(&bsv[o - 12]);
                        Slo += fminf(fmaxf(vlo + bb, -5.0f), 2.0f);
                        Shi += fminf(fmaxf(vhi + bb, -5.0f), 2.0f);
                    }
                }
            Slo += __shfl_xor_sync(0xffffffffu, Slo, 1);
            Slo += __shfl_xor_sync(0xffffffffu, Slo, 2);
            Shi += __shfl_xor_sync(0xffffffffu, Shi, 1);
            Shi += __shfl_xor_sync(0xffffffffu, Shi, 2);
            if (t4 == 0) {
                outF[(m0 + r) * 14 + 12]     = -Slo - 6.0f * LOG2PI;
                outF[(m0 + r) * 14 + 13]     = Slo + 6.0f + 6.0f * LOG2PI;
                outF[(m0 + r + 8) * 14 + 12] = -Shi - 6.0f * LOG2PI;
                outF[(m0 + r + 8) * 14 + 13] = Shi + 6.0f + 6.0f * LOG2PI;
            }
        }
    }
}

// ---------------- launch ----------------
extern "C" void kernel_launch(void* const* d_in, const int* in_sizes, int n_in,
                              void* d_out, int out_size)
{
    const float *x, *h0, *c0, *W_ih, *W_hh, *b_ih, *b_hh, *ln_g, *ln_b;
    const float *W1, *b1, *W2, *b2, *Wm, *bm, *Ws, *bs;
    const int* done;

    if (in_sizes[1] == TT * BB) {
        // setup_inputs dict order
        x = (const float*)d_in[0];  done = (const int*)d_in[1];
        h0 = (const float*)d_in[2]; c0 = (const float*)d_in[3];
        W_ih = (const float*)d_in[4]; W_hh = (const float*)d_in[5];
        b_ih = (const float*)d_in[6]; b_hh = (const float*)d_in[7];
        ln_g = (const float*)d_in[8]; ln_b = (const float*)d_in[9];
        W1 = (const float*)d_in[10]; b1 = (const float*)d_in[11];
        W2 = (const float*)d_in[12]; b2 = (const float*)d_in[13];
        Wm = (const float*)d_in[14]; bm = (const float*)d_in[15];
        Ws = (const float*)d_in[16]; bs = (const float*)d_in[17];
    } else {
        // reference() signature order
        x = (const float*)d_in[0];
        h0 = (const float*)d_in[1]; c0 = (const float*)d_in[2];
        W_ih = (const float*)d_in[3]; W_hh = (const float*)d_in[4];
        b_ih = (const float*)d_in[5]; b_hh = (const float*)d_in[6];
        ln_g = (const float*)d_in[7]; ln_b = (const float*)d_in[8];
        W1 = (const float*)d_in[9];  b1 = (const float*)d_in[10];
        W2 = (const float*)d_in[11]; b2 = (const float*)d_in[12];
        Wm = (const float*)d_in[13]; bm = (const float*)d_in[14];
        Ws = (const float*)d_in[15]; bs = (const float*)d_in[16];
        done = (const int*)d_in[17];
    }

    float* out = (float*)d_out;

    bf16 *p_hb, *p_W1b, *p_W2b, *p_y1;
    cudaGetSymbolAddress((void**)&p_hb, g_hb);
    cudaGetSymbolAddress((void**)&p_W1b, g_W1b);
    cudaGetSymbolAddress((void**)&p_W2b, g_W2b);
    cudaGetSymbolAddress((void**)&p_y1, g_y1);

    const int SM1 = 64 * (HH + 8) * 2 + 2 * 128 * 80;            // 54272
    const int SM2 = 64 * (M1 + 8) * 2 + 2 * 256 * 80;            // 107520

    cudaFuncSetAttribute(lstm_persist, cudaFuncAttributeMaxDynamicSharedMemorySize, SM_TOTAL);
    cudaFuncSetAttribute(gemm_hot<HH, 128, true, false, 8>,
                         cudaFuncAttributeMaxDynamicSharedMemorySize, SM1);
    cudaFuncSetAttribute(gemm_hot<M1, 256, false, true, 16>,
                         cudaFuncAttributeMaxDynamicSharedMemorySize, SM2);

    // 0. single merged prep
    prep_all<<<(PREP_TOTAL + 255) / 256, 256>>>(x, W_hh, W_ih, b_ih, b_hh,
                                                W1, W2, Wm, Ws);

    // 1. persistent cluster LSTM (accurate gates)
    lstm_persist<<<128, 256, SM_TOTAL>>>(h0, c0, done);

    // 2. MLP1 (LN fused in-kernel), 256 threads / 4 CTAs per SM
    gemm_hot<HH, 128, true, false, 8><<<dim3(TB / 64, M1 / 128), 256, SM1>>>(
        p_hb, p_W1b, b1, p_y1, ln_g, ln_b, nullptr, nullptr, nullptr);

    // 3. MLP2 + tensor-core heads, 512 threads (32 warps/SM)
    gemm_hot<M1, 256, false, true, 16><<<dim3(TB / 64, 1), 512, SM2>>>(
        p_y1, p_W2b, b2, nullptr, nullptr, nullptr, bm, bs, out);
}

// round 16
// speedup vs baseline: 1.0208x; 1.0208x over previous
#include <cuda_runtime.h>
#include <cuda_bf16.h>
#include <math.h>
#include <stdint.h>

#define TT 64
#define BB 2048
#define OBS 48
#define HH 256
#define G4 1024
#define KC 304
#define M1 512
#define M2 256
#define TB (TT*BB)
#define LOG2PI 1.8378770664093453f

typedef __nv_bfloat16 bf16;

// ---------------- scratch ----------------
__device__ __align__(16) bf16 g_Wc[G4 * KC];
__device__ float            g_bias[G4];
__device__ __align__(16) bf16 g_W1b[M1 * HH];
__device__ __align__(16) bf16 g_W2b[M2 * M1];
__device__ __align__(16) bf16 g_Whd[32 * M2];        // [Wm|Ws|0] head weights, [o][k]
__device__ __align__(16) bf16 g_xb[(size_t)TB * OBS];
__device__ __align__(16) bf16 g_hb[(size_t)TB * HH];
__device__ __align__(16) bf16 g_y1[(size_t)TB * M1];

// ---------------- helpers ----------------
__device__ __forceinline__ uint32_t bf2_as_u32(__nv_bfloat162 v) {
    return *reinterpret_cast<uint32_t*>(&v);
}

__device__ __forceinline__ void mma16816(float c[4],
    uint32_t a0, uint32_t a1, uint32_t a2, uint32_t a3,
    uint32_t b0, uint32_t b1)
{
    asm volatile(
        "mma.sync.aligned.m16n8k16.row.col.f32.bf16.bf16.f32 "
        "{%0,%1,%2,%3}, {%4,%5,%6,%7}, {%8,%9}, {%0,%1,%2,%3};"
        : "+f"(c[0]), "+f"(c[1]), "+f"(c[2]), "+f"(c[3])
        : "r"(a0), "r"(a1), "r"(a2), "r"(a3), "r"(b0), "r"(b1));
}

__device__ __forceinline__ void ldsm4(uint32_t& r0, uint32_t& r1,
                                      uint32_t& r2, uint32_t& r3, uint32_t addr)
{
    asm volatile("ldmatrix.sync.aligned.m8n8.x4.shared.b16 {%0,%1,%2,%3}, [%4];"
                 : "=r"(r0), "=r"(r1), "=r"(r2), "=r"(r3) : "r"(addr));
}

__device__ __forceinline__ uint32_t smem_u32(const void* p) {
    uint32_t a;
    asm("{ .reg .u64 t; cvta.to.shared.u64 t, %1; cvt.u32.u64 %0, t; }"
        : "=r"(a) : "l"(p));
    return a;
}

// accurate (MUFU-based, ~2 ulp) nonlinearities for the LSTM recurrence
__device__ __forceinline__ float sig_acc(float x) {
    return __fdividef(1.0f, 1.0f + __expf(-x));
}
__device__ __forceinline__ float tanh_acc(float x) {
    float xc = fminf(fmaxf(x, -15.0f), 15.0f);
    float e = __expf(2.0f * xc);
    return __fdividef(e - 1.0f, e + 1.0f);
}

// ---------------- merged prep kernel ----------------
#define XSEG   ((TB * OBS) / 4)
#define WCSEG  (G4 * KC)
#define W12SEG (M1 * HH + M2 * M1)
#define WHDSEG (32 * M2)
#define PREP_TOTAL (XSEG + WCSEG + W12SEG + WHDSEG)

__global__ void prep_all(
    const float* __restrict__ x,
    const float* __restrict__ W_hh, const float* __restrict__ W_ih,
    const float* __restrict__ b_ih, const float* __restrict__ b_hh,
    const float* __restrict__ W1, const float* __restrict__ W2,
    const float* __restrict__ Wm, const float* __restrict__ Ws)
{
    int idx = blockIdx.x * blockDim.x + threadIdx.x;
    if (idx < XSEG) {
        float4 v = *(const float4*)(x + (size_t)idx * 4);
        uint2 p;
        p.x = bf2_as_u32(__floats2bfloat162_rn(v.x, v.y));
        p.y = bf2_as_u32(__floats2bfloat162_rn(v.z, v.w));
        *(uint2*)(g_xb + (size_t)idx * 4) = p;
        return;
    }
    idx -= XSEG;
    if (idx < WCSEG) {
        int n = idx / KC, k = idx % KC;
        int g = n & 3, j = n >> 2;
        float v = (k < HH) ? W_hh[(size_t)(g * HH + j) * HH + k]
                           : W_ih[(size_t)(g * HH + j) * OBS + (k - HH)];
        g_Wc[idx] = __float2bfloat16(v);
        if (k == 0) g_bias[n] = b_ih[g * HH + j] + b_hh[g * HH + j];
        return;
    }
    idx -= WCSEG;
    if (idx < W12SEG) {
        if (idx < M1 * HH) {
            int n = idx / HH, k = idx % HH;
            g_W1b[idx] = __float2bfloat16(W1[(size_t)k * M1 + n]);
        } else {
            int i = idx - M1 * HH;
            int n = i / M1, k = i % M1;
            g_W2b[i] = __float2bfloat16(W2[(size_t)k * M2 + n]);
        }
        return;
    }
    idx -= W12SEG;
    if (idx < WHDSEG) {
        int o = idx / M2, k = idx % M2;
        float v = 0.0f;
        if (o < 12) v = Wm[k * 12 + o];
        else if (o < 24) v = Ws[k * 12 + (o - 12)];
        g_Whd[idx] = __float2bfloat16(v);
    }
}

// ---------------- persistent cluster LSTM (accurate gates; unchanged) ----------------
#define SM_BIAS  0
#define SM_A     1024
#define SM_STAGE 43008
#define SM_B     52224
#define SM_TOTAL 220160
#define ASTR_B 656
#define STG_B  144

__global__ void __launch_bounds__(256, 1) __cluster_dims__(4, 1, 1)
lstm_persist(const float* __restrict__ h0, const float* __restrict__ c0,
             const int* __restrict__ done)
{
    extern __shared__ char smx[];
    const uint32_t smb = smem_u32(smx);

    const int tid = threadIdx.x;
    const int lane = tid & 31, warp = tid >> 5;
    const int wm = warp & 1, wn = warp >> 1;
    const int g8 = lane >> 2, t4 = lane & 3;

    uint32_t rank;
    asm("mov.u32 %0, %%cluster_ctarank;" : "=r"(rank));
    const int b0 = (blockIdx.x >> 2) * 64;
    const int jbase = rank * 64;

    float* bias_s = (float*)(smx + SM_BIAS);
    bias_s[tid] = g_bias[rank * 256 + tid];

    for (int u = tid; u < 256 * 38; u += 256) {
        int n = u / 38, off = u % 38;
        uint4 v = *(const uint4*)((const char*)g_Wc + (size_t)(rank * 256 + n) * 608 + off * 16);
        *(uint4*)(smx + SM_B + n * ASTR_B + off * 16) = v;
    }
    for (int u = tid; u < 4096; u += 256) {
        int row = u >> 6, c4 = u & 63;
        float4 v = *(const float4*)(h0 + (size_t)(b0 + row) * HH + c4 * 4);
        uint2 p;
        p.x = bf2_as_u32(__floats2bfloat162_rn(v.x, v.y));
        p.y = bf2_as_u32(__floats2bfloat162_rn(v.z, v.w));
        *(uint2*)(smx + SM_A + row * ASTR_B + c4 * 8) = p;
    }
    {
        const uint4* xs = (const uint4*)(g_xb + (size_t)b0 * OBS);
        for (int u = tid; u < 384; u += 256) {
            uint4 v = xs[u];
            int e = u * 8, row = e / 48, col = e % 48;
            *(uint4*)(smx + SM_A + row * ASTR_B + 512 + col * 2) = v;
        }
    }
    float creg[16];
#pragma unroll
    for (int am = 0; am < 2; am++)
#pragma unroll
        for (int an = 0; an < 8; an++) {
            int r = wm * 32 + am * 16 + g8 + (t4 & 1) * 8;
            int jl = wn * 16 + an * 2 + (t4 >> 1);
            creg[am * 8 + an] = c0[(size_t)(b0 + r) * HH + jbase + jl];
        }
    __syncthreads();

    const int mi = lane >> 3;
    const int rowoff = ((mi & 1) << 3) + (lane & 7);
    const uint32_t kboff = (uint32_t)((mi >> 1) << 4);
    uint32_t aBase[2], bBase[4];
#pragma unroll
    for (int am = 0; am < 2; am++)
        aBase[am] = smb + SM_A + (wm * 32 + am * 16 + rowoff) * ASTR_B + kboff;
#pragma unroll
    for (int p = 0; p < 4; p++)
        bBase[p] = smb + SM_B + (wn * 64 + p * 16 + rowoff) * ASTR_B + kboff;

    uint32_t peerA[4];
#pragma unroll
    for (int r = 0; r < 4; r++) {
        uint32_t a;
        asm("mapa.shared::cluster.u32 %0, %1, %2;" : "=r"(a) : "r"(smb + SM_A), "r"(r));
        peerA[r] = a;
    }

    const int base_r = wm * 32 + g8;
    int d0, d1, d2, d3;
    {
        const int* dt = done + b0;
        d0 = dt[base_r]; d1 = dt[base_r + 8];
        d2 = dt[base_r + 16]; d3 = dt[base_r + 24];
    }

#pragma unroll 1
    for (int t = 0; t < TT; t++) {
        uint32_t m0 = d0 ? 0u : ~0u, m1 = d1 ? 0u : ~0u;
        uint32_t m2 = d2 ? 0u : ~0u, m3 = d3 ? 0u : ~0u;

        float acc[2][8][4];
#pragma unroll
        for (int i = 0; i < 2; i++)
#pragma unroll
            for (int j = 0; j < 8; j++)
#pragma unroll
                for (int k = 0; k < 4; k++) acc[i][j][k] = 0.0f;

        if (t)
            asm volatile("barrier.cluster.wait.aligned;" ::: "memory");

#pragma unroll
        for (int ch = 0; ch < 19; ch++) {
            uint32_t a[2][4];
            ldsm4(a[0][0], a[0][1], a[0][2], a[0][3], aBase[0] + ch * 32);
            ldsm4(a[1][0], a[1][1], a[1][2], a[1][3], aBase[1] + ch * 32);
            if (ch < 16) {
                a[0][0] &= m0; a[0][2] &= m0; a[0][1] &= m1; a[0][3] &= m1;
                a[1][0] &= m2; a[1][2] &= m2; a[1][1] &= m3; a[1][3] &= m3;
            }
#pragma unroll
            for (int p = 0; p < 4; p++) {
                uint32_t br0, br1, br2, br3;
                ldsm4(br0, br1, br2, br3, bBase[p] + ch * 32);
#pragma unroll
                for (int am = 0; am < 2; am++) {
                    mma16816(acc[am][2 * p],     a[am][0], a[am][1], a[am][2], a[am][3], br0, br2);
                    mma16816(acc[am][2 * p + 1], a[am][0], a[am][1], a[am][2], a[am][3], br1, br3);
                }
            }
        }

        asm volatile("barrier.cluster.arrive.aligned;" ::: "memory");   // B1 arrive

        uint4 xr0, xr1;
        int dn0 = 0, dn1 = 0, dn2 = 0, dn3 = 0;
        const bool hx = (t < TT - 1);
        if (hx) {
            const uint4* xs = (const uint4*)(g_xb + ((size_t)(t + 1) * BB + b0) * OBS);
            xr0 = xs[tid];
            if (tid < 128) xr1 = xs[tid + 256];
            const int* dt = done + (size_t)(t + 1) * BB + b0;
            dn0 = dt[base_r]; dn1 = dt[base_r + 8];
            dn2 = dt[base_r + 16]; dn3 = dt[base_r + 24];
        }

        const bool odd = (t4 & 1);
#pragma unroll
        for (int am = 0; am < 2; am++) {
            const int dlo = (am == 0) ? d0 : d2;
            const int dhi = (am == 0) ? d1 : d3;
            const int dflag = odd ? dhi : dlo;
#pragma unroll
            for (int an = 0; an < 8; an++) {
                float* a = acc[am][an];
                float s0 = odd ? a[0] : a[2];
                float s1 = odd ? a[1] : a[3];
                float e0 = __shfl_xor_sync(0xffffffffu, s0, 1);
                float e1 = __shfl_xor_sync(0xffffffffu, s1, 1);
                float q0 = odd ? e0 : a[0];
                float q1 = odd ? e1 : a[1];
                float q2 = odd ? a[2] : e0;
                float q3 = odd ? a[3] : e1;
                int jl = wn * 16 + an * 2 + (t4 >> 1);
                float4 bb = *(const float4*)&bias_s[jl * 4];
                float gi = q0 + bb.x, gf = q1 + bb.y, gg = q2 + bb.z, go = q3 + bb.w;
                int cell = am * 8 + an;
                float cold = dflag ? 0.0f : creg[cell];
                float cn = sig_acc(gf) * cold + sig_acc(gi) * tanh_acc(gg);
                creg[cell] = cn;
                float hn = sig_acc(go) * tanh_acc(cn);
                int r = wm * 32 + am * 16 + g8 + (odd ? 8 : 0);
                *(bf16*)(smx + SM_STAGE + r * STG_B + jl * 2) = __float2bfloat16(hn);
            }
        }

        if (hx) {
            int e = tid * 8;
            *(uint4*)(smx + SM_A + (e / 48) * ASTR_B + 512 + (e % 48) * 2) = xr0;
            if (tid < 128) {
                int e2 = (tid + 256) * 8;
                *(uint4*)(smx + SM_A + (e2 / 48) * ASTR_B + 512 + (e2 % 48) * 2) = xr1;
            }
        }

        __syncthreads();
        asm volatile("barrier.cluster.wait.aligned;" ::: "memory");     // B1 wait

#pragma unroll
        for (int q = 0; q < 2; q++) {
            int u = tid + q * 256;
            int row = u >> 3, off = u & 7;
            uint4 v = *(const uint4*)(smx + SM_STAGE + row * STG_B + off * 16);
#pragma unroll
            for (int r = 0; r < 4; r++) {
                uint32_t da = peerA[r] + row * ASTR_B + jbase * 2 + off * 16;
                asm volatile("st.shared::cluster.v4.b32 [%0], {%1,%2,%3,%4};"
                             :: "r"(da), "r"(v.x), "r"(v.y), "r"(v.z), "r"(v.w) : "memory");
            }
            *(uint4*)(g_hb + ((size_t)t * BB + b0 + row) * HH + jbase + off * 8) = v;
        }

        asm volatile("barrier.cluster.arrive.aligned;" ::: "memory");   // B2 arrive
        d0 = dn0; d1 = dn1; d2 = dn2; d3 = dn3;
    }
    asm volatile("barrier.cluster.wait.aligned;" ::: "memory");
}

// ---------------- A-hot GEMM; double-buffered B; MR-row tile ----------------
// MR = 64 (2x4 warp grid) or 32 (1x8 warp grid, 3 CTAs/SM for HEADS).
template <int KD, int NT, bool LNA, bool HEADS, int NWARP, int MR, int MINB>
__global__ __launch_bounds__(NWARP * 32, MINB) void gemm_hot(
    const bf16* __restrict__ A, const bf16* __restrict__ Bw,
    const float* __restrict__ bias, bf16* __restrict__ Out,
    const float* __restrict__ gamma, const float* __restrict__ beta,
    const float* __restrict__ bm, const float* __restrict__ bsv,
    float* __restrict__ outF)
{
    constexpr int THREADS = NWARP * 32;
    constexpr int AST = KD + 8;
    constexpr int ASZ = MR * AST * 2;
    constexpr int MW  = MR / 32;             // m-warps (2 or 1)
    constexpr int NW2 = NWARP / MW;          // n-warps
    constexpr int NPW = NT / NW2;            // N cols per warp
    constexpr int PG  = NPW / 16;            // B ldsm groups per warp
    constexpr int AN  = NPW / 8;             // n-atoms per warp
    constexpr int CH  = KD / 32;
    constexpr int BLD = (NT * 4) / THREADS;
    constexpr int BUFB = NT * 80;

    extern __shared__ char sm[];
    char* smA  = sm;
    char* smB0 = sm + ASZ;
    char* smB1 = sm + ASZ + BUFB;
    char* smW  = smB0;                       // HEADS: reuse B region post-loop

    const int tid = threadIdx.x;
    const int lane = tid & 31, warp = tid >> 5;
    const int wm = (MW == 1) ? 0 : (warp & 1);
    const int wn = (MW == 1) ? warp : (warp >> 1);
    const int g8 = lane >> 2, t4 = lane & 3;
    const size_t m0 = (size_t)blockIdx.x * MR;
    const int n0 = blockIdx.y * NT;

    // ---- load A tile (once); LN in-kernel if LNA (requires MR==64, KD==256) ----
    if (LNA) {
#pragma unroll
        for (int it = 0; it < MR * (KD / 8) / THREADS; it++) {
            int u = tid + it * THREADS;
            int row = u >> 5, pos = u & 31;
            uint4 v = *(const uint4*)(A + (m0 + row) * KD + pos * 8);
            __nv_bfloat162* vp = (__nv_bfloat162*)&v;
            float f[8];
#pragma unroll
            for (int q = 0; q < 4; q++) {
                float2 t2 = __bfloat1622float2(vp[q]);
                f[2 * q] = t2.x; f[2 * q + 1] = t2.y;
            }
            float s = 0.0f, s2 = 0.0f;
#pragma unroll
            for (int q = 0; q < 8; q++) { s += f[q]; s2 += f[q] * f[q]; }
#pragma unroll
            for (int o = 16; o; o >>= 1) {
                s  += __shfl_xor_sync(0xffffffffu, s, o);
                s2 += __shfl_xor_sync(0xffffffffu, s2, o);
            }
            float mu = s * (1.0f / HH);
            float rs = rsqrtf(s2 * (1.0f / HH) - mu * mu + 1e-5f);
#pragma unroll
            for (int q = 0; q < 8; q++) {
                int c = pos * 8 + q;
                f[q] = (f[q] - mu) * rs * __ldg(&gamma[c]) + __ldg(&beta[c]);
            }
#pragma unroll
            for (int q = 0; q < 4; q++)
                vp[q] = __floats2bfloat162_rn(f[2 * q], f[2 * q + 1]);
            *(uint4*)(smA + row * AST * 2 + pos * 16) = v;
        }
    } else {
        for (int u = tid; u < MR * (KD / 8); u += THREADS) {
            int row = u / (KD / 8), pos = u % (KD / 8);
            uint4 v = *(const uint4*)(A + (m0 + row) * KD + pos * 8);
            *(uint4*)(smA + row * AST * 2 + pos * 16) = v;
        }
    }

    uint4 breg[BLD];
#pragma unroll
    for (int i = 0; i < BLD; i++) {
        int u = tid + i * THREADS;
        int row = u >> 2, q = u & 3;
        breg[i] = *(const uint4*)(Bw + (size_t)(n0 + row) * KD + q * 8);
    }

    float acc[2][AN][4];
#pragma unroll
    for (int i = 0; i < 2; i++)
#pragma unroll
        for (int j = 0; j < AN; j++)
#pragma unroll
            for (int k = 0; k < 4; k++) acc[i][j][k] = 0.0f;

    const int mi = lane >> 3;
    const int rowoff = ((mi & 1) << 3) + (lane & 7);
    const uint32_t kb16 = (uint32_t)((mi >> 1) << 4);
    const uint32_t smAu = smem_u32(smA);
    const uint32_t smB0u = smem_u32(smB0);
    uint32_t aB[2], bB[PG];
#pragma unroll
    for (int am = 0; am < 2; am++)
        aB[am] = smAu + (wm * 32 + am * 16 + rowoff) * (AST * 2) + kb16;
#pragma unroll
    for (int p = 0; p < PG; p++)
        bB[p] = smB0u + (wn * NPW + p * 16 + rowoff) * 80 + kb16;

    // ---- K loop: one sync per chunk, double-buffered B ----
#pragma unroll 1
    for (int c = 0; c < CH; c++) {
        const uint32_t bufOff = (c & 1) ? (uint32_t)BUFB : 0u;
        char* bufc = (c & 1) ? smB1 : smB0;
#pragma unroll
        for (int i = 0; i < BLD; i++) {
            int u = tid + i * THREADS;
            int row = u >> 2, q = u & 3;
            *(uint4*)(bufc + row * 80 + q * 16) = breg[i];
        }
        __syncthreads();
        if (c + 1 < CH) {
#pragma unroll
            for (int i = 0; i < BLD; i++) {
                int u = tid + i * THREADS;
                int row = u >> 2, q = u & 3;
                breg[i] = *(const uint4*)(Bw + (size_t)(n0 + row) * KD + (c + 1) * 32 + q * 8);
            }
        }
#pragma unroll
        for (int ks = 0; ks < 2; ks++) {
            int s = c * 2 + ks;
            uint32_t a[2][4];
            ldsm4(a[0][0], a[0][1], a[0][2], a[0][3], aB[0] + s * 32);
            ldsm4(a[1][0], a[1][1], a[1][2], a[1][3], aB[1] + s * 32);
#pragma unroll
            for (int p = 0; p < PG; p++) {
                uint32_t br0, br1, br2, br3;
                ldsm4(br0, br1, br2, br3, bB[p] + bufOff + ks * 32);
#pragma unroll
                for (int am = 0; am < 2; am++) {
                    mma16816(acc[am][2 * p],     a[am][0], a[am][1], a[am][2], a[am][3], br0, br2);
                    mma16816(acc[am][2 * p + 1], a[am][0], a[am][1], a[am][2], a[am][3], br1, br3);
                }
            }
        }
    }

    if (!HEADS) {
#pragma unroll
        for (int am = 0; am < 2; am++)
#pragma unroll
            for (int an = 0; an < AN; an++) {
                size_t r = m0 + wm * 32 + am * 16 + g8;
                int c = n0 + wn * NPW + an * 8 + t4 * 2;
                float bc0 = __ldg(&bias[c]), bc1 = __ldg(&bias[c + 1]);
                float v0 = acc[am][an][0] + bc0;
                float v1 = acc[am][an][1] + bc1;
                v0 = (v0 > 0.0f) ? v0 : expm1f(v0);
                v1 = (v1 > 0.0f) ? v1 : expm1f(v1);
                *(__nv_bfloat162*)(Out + r * (M1) + c) = __floats2bfloat162_rn(v0, v1);
                float v2 = acc[am][an][2] + bc0;
                float v3 = acc[am][an][3] + bc1;
                v2 = (v2 > 0.0f) ? v2 : expm1f(v2);
                v3 = (v3 > 0.0f) ? v3 : expm1f(v3);
                *(__nv_bfloat162*)(Out + (r + 8) * (M1) + c) = __floats2bfloat162_rn(v2, v3);
            }
    } else {
        // ---- tensor-core heads epilogue (MR rows) ----
        __syncthreads();
        char* ys = smA;
        for (int u = tid; u < 1024; u += THREADS) {
            int row = u >> 5, q = u & 31;
            *(uint4*)(smW + row * 528 + q * 16) = *(const uint4*)(g_Whd + row * M2 + q * 8);
        }
#pragma unroll
        for (int am = 0; am < 2; am++)
#pragma unroll
            for (int an = 0; an < AN; an++) {
                int r = wm * 32 + am * 16 + g8;
                int c = wn * NPW + an * 8 + t4 * 2;
                float bc0 = __ldg(&bias[c]), bc1 = __ldg(&bias[c + 1]);
                float v0 = acc[am][an][0] + bc0;
                float v1 = acc[am][an][1] + bc1;
                v0 = (v0 > 0.0f) ? v0 : expm1f(v0);
                v1 = (v1 > 0.0f) ? v1 : expm1f(v1);
                *(__nv_bfloat162*)(ys + r * 528 + c * 2) = __floats2bfloat162_rn(v0, v1);
                float v2 = acc[am][an][2] + bc0;
                float v3 = acc[am][an][3] + bc1;
                v2 = (v2 > 0.0f) ? v2 : expm1f(v2);
                v3 = (v3 > 0.0f) ? v3 : expm1f(v3);
                *(__nv_bfloat162*)(ys + (r + 8) * 528 + c * 2) = __floats2bfloat162_rn(v2, v3);
            }
        __syncthreads();

        if (warp < MR / 16) {
            const uint32_t aH = smem_u32(ys) + (warp * 16 + rowoff) * 528 + kb16;
            const uint32_t smWu = smem_u32(smW);
            const uint32_t bH0 = smWu + rowoff * 528 + kb16;
            const uint32_t bH1 = smWu + (16 + rowoff) * 528 + kb16;

            float ah[4][4];
#pragma unroll
            for (int i = 0; i < 4; i++)
#pragma unroll
                for (int k = 0; k < 4; k++) ah[i][k] = 0.0f;

#pragma unroll
            for (int s = 0; s < 16; s++) {
                uint32_t a0, a1, a2, a3;
                ldsm4(a0, a1, a2, a3, aH + s * 32);
                uint32_t b0, b1, b2, b3;
                ldsm4(b0, b1, b2, b3, bH0 + s * 32);
                mma16816(ah[0], a0, a1, a2, a3, b0, b2);
                mma16816(ah[1], a0, a1, a2, a3, b1, b3);
                ldsm4(b0, b1, b2, b3, bH1 + s * 32);
                mma16816(ah[2], a0, a1, a2, a3, b0, b2);
                mma16816(ah[3], a0, a1, a2, a3, b1, b3);
            }

            int r = warp * 16 + g8;
            float Slo = 0.0f, Shi = 0.0f;
#pragma unroll
            for (int an = 0; an < 4; an++)
#pragma unroll
                for (int j = 0; j < 2; j++) {
                    int o = an * 8 + t4 * 2 + j;
                    float vlo = ah[an][j], vhi = ah[an][2 + j];
                    if (o < 12) {
                        float bb = __ldg(&bm[o]);
                        outF[(m0 + r) * 14 + o]     = vlo + bb;
                        outF[(m0 + r + 8) * 14 + o] = vhi + bb;
                    } else if (o < 24) {
                        float bb = __ldg(&bsv[o - 12]);
                        Slo += fminf(fmaxf(vlo + bb, -5.0f), 2.0f);
                        Shi += fminf(fmaxf(vhi + bb, -5.0f), 2.0f);
                    }
                }
            Slo += __shfl_xor_sync(0xffffffffu, Slo, 1);
            Slo += __shfl_xor_sync(0xffffffffu, Slo, 2);
            Shi += __shfl_xor_sync(0xffffffffu, Shi, 1);
            Shi += __shfl_xor_sync(0xffffffffu, Shi, 2);
            if (t4 == 0) {
                outF[(m0 + r) * 14 + 12]     = -Slo - 6.0f * LOG2PI;
                outF[(m0 + r) * 14 + 13]     = Slo + 6.0f + 6.0f * LOG2PI;
                outF[(m0 + r + 8) * 14 + 12] = -Shi - 6.0f * LOG2PI;
                outF[(m0 + r + 8) * 14 + 13] = Shi + 6.0f + 6.0f * LOG2PI;
            }
        }
    }
}

// ---------------- launch ----------------
extern "C" void kernel_launch(void* const* d_in, const int* in_sizes, int n_in,
                              void* d_out, int out_size)
{
    const float *x, *h0, *c0, *W_ih, *W_hh, *b_ih, *b_hh, *ln_g, *ln_b;
    const float *W1, *b1, *W2, *b2, *Wm, *bm, *Ws, *bs;
    const int* done;

    if (in_sizes[1] == TT * BB) {
        // setup_inputs dict order
        x = (const float*)d_in[0];  done = (const int*)d_in[1];
        h0 = (const float*)d_in[2]; c0 = (const float*)d_in[3];
        W_ih = (const float*)d_in[4]; W_hh = (const float*)d_in[5];
        b_ih = (const float*)d_in[6]; b_hh = (const float*)d_in[7];
        ln_g = (const float*)d_in[8]; ln_b = (const float*)d_in[9];
        W1 = (const float*)d_in[10]; b1 = (const float*)d_in[11];
        W2 = (const float*)d_in[12]; b2 = (const float*)d_in[13];
        Wm = (const float*)d_in[14]; bm = (const float*)d_in[15];
        Ws = (const float*)d_in[16]; bs = (const float*)d_in[17];
    } else {
        // reference() signature order
        x = (const float*)d_in[0];
        h0 = (const float*)d_in[1]; c0 = (const float*)d_in[2];
        W_ih = (const float*)d_in[3]; W_hh = (const float*)d_in[4];
        b_ih = (const float*)d_in[5]; b_hh = (const float*)d_in[6];
        ln_g = (const float*)d_in[7]; ln_b = (const float*)d_in[8];
        W1 = (const float*)d_in[9];  b1 = (const float*)d_in[10];
        W2 = (const float*)d_in[11]; b2 = (const float*)d_in[12];
        Wm = (const float*)d_in[13]; bm = (const float*)d_in[14];
        Ws = (const float*)d_in[15]; bs = (const float*)d_in[16];
        done = (const int*)d_in[17];
    }

    float* out = (float*)d_out;

    bf16 *p_hb, *p_W1b, *p_W2b, *p_y1;
    cudaGetSymbolAddress((void**)&p_hb, g_hb);
    cudaGetSymbolAddress((void**)&p_W1b, g_W1b);
    cudaGetSymbolAddress((void**)&p_W2b, g_W2b);
    cudaGetSymbolAddress((void**)&p_y1, g_y1);

    const int SM1 = 64 * (HH + 8) * 2 + 2 * 128 * 80;            // 54272 (4 CTAs/SM)
    const int SM2 = 32 * (M1 + 8) * 2 + 2 * 256 * 80;            // 74240 (3 CTAs/SM)

    cudaFuncSetAttribute(lstm_persist, cudaFuncAttributeMaxDynamicSharedMemorySize, SM_TOTAL);
    cudaFuncSetAttribute(gemm_hot<HH, 128, true, false, 8, 64, 4>,
                         cudaFuncAttributeMaxDynamicSharedMemorySize, SM1);
    cudaFuncSetAttribute(gemm_hot<M1, 256, false, true, 8, 32, 3>,
                         cudaFuncAttributeMaxDynamicSharedMemorySize, SM2);

    // 0. single merged prep
    prep_all<<<(PREP_TOTAL + 255) / 256, 256>>>(x, W_hh, W_ih, b_ih, b_hh,
                                                W1, W2, Wm, Ws);

    // 1. persistent cluster LSTM (accurate gates)
    lstm_persist<<<128, 256, SM_TOTAL>>>(h0, c0, done);

    // 2. MLP1 (LN fused in-kernel), 64-row tiles, 4 CTAs/SM
    gemm_hot<HH, 128, true, false, 8, 64, 4><<<dim3(TB / 64, M1 / 128), 256, SM1>>>(
        p_hb, p_W1b, b1, p_y1, ln_g, ln_b, nullptr, nullptr, nullptr);

    // 3. MLP2 + tensor-core heads, 32-row tiles, 3 CTAs/SM (24 warps)
    gemm_hot<M1, 256, false, true, 8, 32, 3><<<dim3(TB / 32, 1), 256, SM2>>>(
        p_y1, p_W2b, b2, nullptr, nullptr, nullptr, bm, bs, out);
}

// round 17
// speedup vs baseline: 1.1945x; 1.1701x over previous
#include <cuda_runtime.h>
#include <cuda_bf16.h>
#include <math.h>
#include <stdint.h>

#define TT 64
#define BB 2048
#define OBS 48
#define HH 256
#define G4 1024
#define KC 304
#define M1 512
#define M2 256
#define TB (TT*BB)
#define LOG2PI 1.8378770664093453f

typedef __nv_bfloat16 bf16;

// ---------------- scratch ----------------
__device__ __align__(16) bf16 g_Wc[G4 * KC];
__device__ float            g_bias[G4];
__device__ __align__(16) uint4 g_W1f[16 * 32 * 32];  // W1 mma fragments [s][g][lane]
__device__ __align__(16) uint4 g_W2f[32 * 16 * 32];  // W2 mma fragments [s][g][lane]
__device__ __align__(16) bf16 g_Whd[32 * M2];        // [Wm|Ws|0] head weights, [o][k]
__device__ __align__(16) bf16 g_xb[(size_t)TB * OBS];
__device__ __align__(16) bf16 g_hb[(size_t)TB * HH];
__device__ __align__(16) bf16 g_y1[(size_t)TB * M1];

// ---------------- helpers ----------------
__device__ __forceinline__ uint32_t bf2_as_u32(__nv_bfloat162 v) {
    return *reinterpret_cast<uint32_t*>(&v);
}

__device__ __forceinline__ void mma16816(float c[4],
    uint32_t a0, uint32_t a1, uint32_t a2, uint32_t a3,
    uint32_t b0, uint32_t b1)
{
    asm volatile(
        "mma.sync.aligned.m16n8k16.row.col.f32.bf16.bf16.f32 "
        "{%0,%1,%2,%3}, {%4,%5,%6,%7}, {%8,%9}, {%0,%1,%2,%3};"
        : "+f"(c[0]), "+f"(c[1]), "+f"(c[2]), "+f"(c[3])
        : "r"(a0), "r"(a1), "r"(a2), "r"(a3), "r"(b0), "r"(b1));
}

__device__ __forceinline__ void ldsm4(uint32_t& r0, uint32_t& r1,
                                      uint32_t& r2, uint32_t& r3, uint32_t addr)
{
    asm volatile("ldmatrix.sync.aligned.m8n8.x4.shared.b16 {%0,%1,%2,%3}, [%4];"
                 : "=r"(r0), "=r"(r1), "=r"(r2), "=r"(r3) : "r"(addr));
}

__device__ __forceinline__ uint32_t smem_u32(const void* p) {
    uint32_t a;
    asm("{ .reg .u64 t; cvta.to.shared.u64 t, %1; cvt.u32.u64 %0, t; }"
        : "=r"(a) : "l"(p));
    return a;
}

// accurate (MUFU-based, ~2 ulp) nonlinearities for the LSTM recurrence
__device__ __forceinline__ float sig_acc(float x) {
    return __fdividef(1.0f, 1.0f + __expf(-x));
}
__device__ __forceinline__ float tanh_acc(float x) {
    float xc = fminf(fmaxf(x, -15.0f), 15.0f);
    float e = __expf(2.0f * xc);
    return __fdividef(e - 1.0f, e + 1.0f);
}

// ---------------- merged prep kernel ----------------
#define XSEG   ((TB * OBS) / 4)
#define WCSEG  (G4 * KC)
#define W1FSEG (16 * 32 * 32)
#define W2FSEG (32 * 16 * 32)
#define WHDSEG (32 * M2)
#define PREP_TOTAL (XSEG + WCSEG + W1FSEG + W2FSEG + WHDSEG)

__global__ void prep_all(
    const float* __restrict__ x,
    const float* __restrict__ W_hh, const float* __restrict__ W_ih,
    const float* __restrict__ b_ih, const float* __restrict__ b_hh,
    const float* __restrict__ W1, const float* __restrict__ W2,
    const float* __restrict__ Wm, const float* __restrict__ Ws)
{
    int idx = blockIdx.x * blockDim.x + threadIdx.x;
    if (idx < XSEG) {
        float4 v = *(const float4*)(x + (size_t)idx * 4);
        uint2 p;
        p.x = bf2_as_u32(__floats2bfloat162_rn(v.x, v.y));
        p.y = bf2_as_u32(__floats2bfloat162_rn(v.z, v.w));
        *(uint2*)(g_xb + (size_t)idx * 4) = p;
        return;
    }
    idx -= XSEG;
    if (idx < WCSEG) {
        int n = idx / KC, k = idx % KC;
        int g = n & 3, j = n >> 2;
        float v = (k < HH) ? W_hh[(size_t)(g * HH + j) * HH + k]
                           : W_ih[(size_t)(g * HH + j) * OBS + (k - HH)];
        g_Wc[idx] = __float2bfloat16(v);
        if (k == 0) g_bias[n] = b_ih[g * HH + j] + b_hh[g * HH + j];
        return;
    }
    idx -= WCSEG;
    if (idx < W1FSEG) {
        // W1 fragments: B[n][k] = W1[k][n]; layout [s(16)][g(32)][lane(32)]
        int lane = idx & 31;
        int g = (idx >> 5) & 31;
        int s = idx >> 10;
        uint32_t q[4];
#pragma unroll
        for (int qi = 0; qi < 4; qi++) {
            int n = g * 16 + ((qi & 1) ? 8 : 0) + (lane >> 2);
            int k = s * 16 + ((qi & 2) ? 8 : 0) + 2 * (lane & 3);
            q[qi] = bf2_as_u32(__floats2bfloat162_rn(
                W1[(size_t)k * M1 + n], W1[(size_t)(k + 1) * M1 + n]));
        }
        g_W1f[idx] = make_uint4(q[0], q[1], q[2], q[3]);
        return;
    }
    idx -= W1FSEG;
    if (idx < W2FSEG) {
        // W2 fragments: B[n][k] = W2[k][n]; layout [s(32)][g(16)][lane(32)]
        int lane = idx & 31;
        int g = (idx >> 5) & 15;
        int s = idx >> 9;
        uint32_t q[4];
#pragma unroll
        for (int qi = 0; qi < 4; qi++) {
            int n = g * 16 + ((qi & 1) ? 8 : 0) + (lane >> 2);
            int k = s * 16 + ((qi & 2) ? 8 : 0) + 2 * (lane & 3);
            q[qi] = bf2_as_u32(__floats2bfloat162_rn(
                W2[(size_t)k * M2 + n], W2[(size_t)(k + 1) * M2 + n]));
        }
        g_W2f[idx] = make_uint4(q[0], q[1], q[2], q[3]);
        return;
    }
    idx -= W2FSEG;
    if (idx < WHDSEG) {
        int o = idx / M2, k = idx % M2;
        float v = 0.0f;
        if (o < 12) v = Wm[k * 12 + o];
        else if (o < 24) v = Ws[k * 12 + (o - 12)];
        g_Whd[idx] = __float2bfloat16(v);
    }
}

// ---------------- persistent cluster LSTM (accurate gates; unchanged) ----------------
#define SM_BIAS  0
#define SM_A     1024
#define SM_STAGE 43008
#define SM_B     52224
#define SM_TOTAL 220160
#define ASTR_B 656
#define STG_B  144

__global__ void __launch_bounds__(256, 1) __cluster_dims__(4, 1, 1)
lstm_persist(const float* __restrict__ h0, const float* __restrict__ c0,
             const int* __restrict__ done)
{
    extern __shared__ char smx[];
    const uint32_t smb = smem_u32(smx);

    const int tid = threadIdx.x;
    const int lane = tid & 31, warp = tid >> 5;
    const int wm = warp & 1, wn = warp >> 1;
    const int g8 = lane >> 2, t4 = lane & 3;

    uint32_t rank;
    asm("mov.u32 %0, %%cluster_ctarank;" : "=r"(rank));
    const int b0 = (blockIdx.x >> 2) * 64;
    const int jbase = rank * 64;

    float* bias_s = (float*)(smx + SM_BIAS);
    bias_s[tid] = g_bias[rank * 256 + tid];

    for (int u = tid; u < 256 * 38; u += 256) {
        int n = u / 38, off = u % 38;
        uint4 v = *(const uint4*)((const char*)g_Wc + (size_t)(rank * 256 + n) * 608 + off * 16);
        *(uint4*)(smx + SM_B + n * ASTR_B + off * 16) = v;
    }
    for (int u = tid; u < 4096; u += 256) {
        int row = u >> 6, c4 = u & 63;
        float4 v = *(const float4*)(h0 + (size_t)(b0 + row) * HH + c4 * 4);
        uint2 p;
        p.x = bf2_as_u32(__floats2bfloat162_rn(v.x, v.y));
        p.y = bf2_as_u32(__floats2bfloat162_rn(v.z, v.w));
        *(uint2*)(smx + SM_A + row * ASTR_B + c4 * 8) = p;
    }
    {
        const uint4* xs = (const uint4*)(g_xb + (size_t)b0 * OBS);
        for (int u = tid; u < 384; u += 256) {
            uint4 v = xs[u];
            int e = u * 8, row = e / 48, col = e % 48;
            *(uint4*)(smx + SM_A + row * ASTR_B + 512 + col * 2) = v;
        }
    }
    float creg[16];
#pragma unroll
    for (int am = 0; am < 2; am++)
#pragma unroll
        for (int an = 0; an < 8; an++) {
            int r = wm * 32 + am * 16 + g8 + (t4 & 1) * 8;
            int jl = wn * 16 + an * 2 + (t4 >> 1);
            creg[am * 8 + an] = c0[(size_t)(b0 + r) * HH + jbase + jl];
        }
    __syncthreads();

    const int mi = lane >> 3;
    const int rowoff = ((mi & 1) << 3) + (lane & 7);
    const uint32_t kboff = (uint32_t)((mi >> 1) << 4);
    uint32_t aBase[2], bBase[4];
#pragma unroll
    for (int am = 0; am < 2; am++)
        aBase[am] = smb + SM_A + (wm * 32 + am * 16 + rowoff) * ASTR_B + kboff;
#pragma unroll
    for (int p = 0; p < 4; p++)
        bBase[p] = smb + SM_B + (wn * 64 + p * 16 + rowoff) * ASTR_B + kboff;

    uint32_t peerA[4];
#pragma unroll
    for (int r = 0; r < 4; r++) {
        uint32_t a;
        asm("mapa.shared::cluster.u32 %0, %1, %2;" : "=r"(a) : "r"(smb + SM_A), "r"(r));
        peerA[r] = a;
    }

    const int base_r = wm * 32 + g8;
    int d0, d1, d2, d3;
    {
        const int* dt = done + b0;
        d0 = dt[base_r]; d1 = dt[base_r + 8];
        d2 = dt[base_r + 16]; d3 = dt[base_r + 24];
    }

#pragma unroll 1
    for (int t = 0; t < TT; t++) {
        uint32_t m0 = d0 ? 0u : ~0u, m1 = d1 ? 0u : ~0u;
        uint32_t m2 = d2 ? 0u : ~0u, m3 = d3 ? 0u : ~0u;

        float acc[2][8][4];
#pragma unroll
        for (int i = 0; i < 2; i++)
#pragma unroll
            for (int j = 0; j < 8; j++)
#pragma unroll
                for (int k = 0; k < 4; k++) acc[i][j][k] = 0.0f;

        if (t)
            asm volatile("barrier.cluster.wait.aligned;" ::: "memory");

#pragma unroll
        for (int ch = 0; ch < 19; ch++) {
            uint32_t a[2][4];
            ldsm4(a[0][0], a[0][1], a[0][2], a[0][3], aBase[0] + ch * 32);
            ldsm4(a[1][0], a[1][1], a[1][2], a[1][3], aBase[1] + ch * 32);
            if (ch < 16) {
                a[0][0] &= m0; a[0][2] &= m0; a[0][1] &= m1; a[0][3] &= m1;
                a[1][0] &= m2; a[1][2] &= m2; a[1][1] &= m3; a[1][3] &= m3;
            }
#pragma unroll
            for (int p = 0; p < 4; p++) {
                uint32_t br0, br1, br2, br3;
                ldsm4(br0, br1, br2, br3, bBase[p] + ch * 32);
#pragma unroll
                for (int am = 0; am < 2; am++) {
                    mma16816(acc[am][2 * p],     a[am][0], a[am][1], a[am][2], a[am][3], br0, br2);
                    mma16816(acc[am][2 * p + 1], a[am][0], a[am][1], a[am][2], a[am][3], br1, br3);
                }
            }
        }

        asm volatile("barrier.cluster.arrive.aligned;" ::: "memory");   // B1 arrive

        uint4 xr0, xr1;
        int dn0 = 0, dn1 = 0, dn2 = 0, dn3 = 0;
        const bool hx = (t < TT - 1);
        if (hx) {
            const uint4* xs = (const uint4*)(g_xb + ((size_t)(t + 1) * BB + b0) * OBS);
            xr0 = xs[tid];
            if (tid < 128) xr1 = xs[tid + 256];
            const int* dt = done + (size_t)(t + 1) * BB + b0;
            dn0 = dt[base_r]; dn1 = dt[base_r + 8];
            dn2 = dt[base_r + 16]; dn3 = dt[base_r + 24];
        }

        const bool odd = (t4 & 1);
#pragma unroll
        for (int am = 0; am < 2; am++) {
            const int dlo = (am == 0) ? d0 : d2;
            const int dhi = (am == 0) ? d1 : d3;
            const int dflag = odd ? dhi : dlo;
#pragma unroll
            for (int an = 0; an < 8; an++) {
                float* a = acc[am][an];
                float s0 = odd ? a[0] : a[2];
                float s1 = odd ? a[1] : a[3];
                float e0 = __shfl_xor_sync(0xffffffffu, s0, 1);
                float e1 = __shfl_xor_sync(0xffffffffu, s1, 1);
                float q0 = odd ? e0 : a[0];
                float q1 = odd ? e1 : a[1];
                float q2 = odd ? a[2] : e0;
                float q3 = odd ? a[3] : e1;
                int jl = wn * 16 + an * 2 + (t4 >> 1);
                float4 bb = *(const float4*)&bias_s[jl * 4];
                float gi = q0 + bb.x, gf = q1 + bb.y, gg = q2 + bb.z, go = q3 + bb.w;
                int cell = am * 8 + an;
                float cold = dflag ? 0.0f : creg[cell];
                float cn = sig_acc(gf) * cold + sig_acc(gi) * tanh_acc(gg);
                creg[cell] = cn;
                float hn = sig_acc(go) * tanh_acc(cn);
                int r = wm * 32 + am * 16 + g8 + (odd ? 8 : 0);
                *(bf16*)(smx + SM_STAGE + r * STG_B + jl * 2) = __float2bfloat16(hn);
            }
        }

        if (hx) {
            int e = tid * 8;
            *(uint4*)(smx + SM_A + (e / 48) * ASTR_B + 512 + (e % 48) * 2) = xr0;
            if (tid < 128) {
                int e2 = (tid + 256) * 8;
                *(uint4*)(smx + SM_A + (e2 / 48) * ASTR_B + 512 + (e2 % 48) * 2) = xr1;
            }
        }

        __syncthreads();
        asm volatile("barrier.cluster.wait.aligned;" ::: "memory");     // B1 wait

#pragma unroll
        for (int q = 0; q < 2; q++) {
            int u = tid + q * 256;
            int row = u >> 3, off = u & 7;
            uint4 v = *(const uint4*)(smx + SM_STAGE + row * STG_B + off * 16);
#pragma unroll
            for (int r = 0; r < 4; r++) {
                uint32_t da = peerA[r] + row * ASTR_B + jbase * 2 + off * 16;
                asm volatile("st.shared::cluster.v4.b32 [%0], {%1,%2,%3,%4};"
                             :: "r"(da), "r"(v.x), "r"(v.y), "r"(v.z), "r"(v.w) : "memory");
            }
            *(uint4*)(g_hb + ((size_t)t * BB + b0 + row) * HH + jbase + off * 8) = v;
        }

        asm volatile("barrier.cluster.arrive.aligned;" ::: "memory");   // B2 arrive
        d0 = dn0; d1 = dn1; d2 = dn2; d3 = dn3;
    }
    asm volatile("barrier.cluster.wait.aligned;" ::: "memory");
}

// ---------------- A-hot GEMM; B fragments direct from L2 (no B smem, no K-loop syncs) ----
// MR=64, warp grid 2m x 4n, 256 threads.
#define GSTEP(S, BARR) do {                                                   \
    uint32_t a_[2][4];                                                        \
    ldsm4(a_[0][0], a_[0][1], a_[0][2], a_[0][3], aB[0] + (S) * 32);          \
    ldsm4(a_[1][0], a_[1][1], a_[1][2], a_[1][3], aB[1] + (S) * 32);          \
    _Pragma("unroll")                                                         \
    for (int p_ = 0; p_ < PG; p_++) {                                         \
        _Pragma("unroll")                                                     \
        for (int am_ = 0; am_ < 2; am_++) {                                   \
            mma16816(acc[am_][2 * p_],     a_[am_][0], a_[am_][1], a_[am_][2],\
                     a_[am_][3], BARR[p_].x, BARR[p_].z);                     \
            mma16816(acc[am_][2 * p_ + 1], a_[am_][0], a_[am_][1], a_[am_][2],\
                     a_[am_][3], BARR[p_].y, BARR[p_].w);                     \
        }                                                                     \
    }                                                                         \
} while (0)

template <int KD, int NT, bool LNA, bool HEADS, int NGT, int MINB>
__global__ __launch_bounds__(256, MINB) void gemm_reg(
    const bf16* __restrict__ A, const uint4* __restrict__ Bf,
    const float* __restrict__ bias, bf16* __restrict__ Out,
    const float* __restrict__ gamma, const float* __restrict__ beta,
    const float* __restrict__ bm, const float* __restrict__ bsv,
    float* __restrict__ outF)
{
    constexpr int AST = KD + 8;
    constexpr int ASZ = 64 * AST * 2;
    constexpr int NPW = NT / 4;              // N cols per warp
    constexpr int PG  = NPW / 16;            // fragment groups per warp
    constexpr int AN  = NPW / 8;             // n-atoms per warp
    constexpr int STEPS = KD / 16;

    extern __shared__ char sm[];
    char* smA = sm;
    char* smW = sm + ASZ;                    // HEADS only

    const int tid = threadIdx.x;
    const int lane = tid & 31, warp = tid >> 5;
    const int wm = warp & 1, wn = warp >> 1;
    const int g8 = lane >> 2, t4 = lane & 3;
    const size_t m0 = (size_t)blockIdx.x * 64;
    const int n0 = blockIdx.y * NT;

    // ---- load A tile (once); LN in-kernel if LNA (KD==256) ----
    if (LNA) {
#pragma unroll
        for (int it = 0; it < 64 * (KD / 8) / 256; it++) {
            int u = tid + it * 256;
            int row = u >> 5, pos = u & 31;
            uint4 v = *(const uint4*)(A + (m0 + row) * KD + pos * 8);
            __nv_bfloat162* vp = (__nv_bfloat162*)&v;
            float f[8];
#pragma unroll
            for (int q = 0; q < 4; q++) {
                float2 t2 = __bfloat1622float2(vp[q]);
                f[2 * q] = t2.x; f[2 * q + 1] = t2.y;
            }
            float s = 0.0f, s2 = 0.0f;
#pragma unroll
            for (int q = 0; q < 8; q++) { s += f[q]; s2 += f[q] * f[q]; }
#pragma unroll
            for (int o = 16; o; o >>= 1) {
                s  += __shfl_xor_sync(0xffffffffu, s, o);
                s2 += __shfl_xor_sync(0xffffffffu, s2, o);
            }
            float mu = s * (1.0f / HH);
            float rs = rsqrtf(s2 * (1.0f / HH) - mu * mu + 1e-5f);
#pragma unroll
            for (int q = 0; q < 8; q++) {
                int c = pos * 8 + q;
                f[q] = (f[q] - mu) * rs * __ldg(&gamma[c]) + __ldg(&beta[c]);
            }
#pragma unroll
            for (int q = 0; q < 4; q++)
                vp[q] = __floats2bfloat162_rn(f[2 * q], f[2 * q + 1]);
            *(uint4*)(smA + row * AST * 2 + pos * 16) = v;
        }
    } else {
        for (int u = tid; u < 64 * (KD / 8); u += 256) {
            int row = u / (KD / 8), pos = u % (KD / 8);
            uint4 v = *(const uint4*)(A + (m0 + row) * KD + pos * 8);
            *(uint4*)(smA + row * AST * 2 + pos * 16) = v;
        }
    }
    __syncthreads();                         // the ONLY pre-loop sync

    const int mi = lane >> 3;
    const int rowoff = ((mi & 1) << 3) + (lane & 7);
    const uint32_t kb16 = (uint32_t)((mi >> 1) << 4);
    const uint32_t smAu = smem_u32(smA);
    uint32_t aB[2];
#pragma unroll
    for (int am = 0; am < 2; am++)
        aB[am] = smAu + (wm * 32 + am * 16 + rowoff) * (AST * 2) + kb16;

    // B fragment base: [s][g][lane]; this warp's groups start at gbase
    const int gbase = n0 / 16 + wn * PG;
    const uint4* bbase = Bf + (size_t)gbase * 32 + lane;
    // step stride in uint4s:
    const size_t sstr = (size_t)NGT * 32;

    float acc[2][AN][4];
#pragma unroll
    for (int i = 0; i < 2; i++)
#pragma unroll
        for (int j = 0; j < AN; j++)
#pragma unroll
            for (int k = 0; k < 4; k++) acc[i][j][k] = 0.0f;

    uint4 b0[PG];
#pragma unroll
    for (int p = 0; p < PG; p++) b0[p] = __ldg(bbase + p * 32);

#pragma unroll 1
    for (int s2 = 0; s2 < STEPS; s2 += 2) {
        uint4 b1[PG];
#pragma unroll
        for (int p = 0; p < PG; p++)
            b1[p] = __ldg(bbase + (size_t)(s2 + 1) * sstr + p * 32);
        GSTEP(s2, b0);
        if (s2 + 2 < STEPS) {
#pragma unroll
            for (int p = 0; p < PG; p++)
                b0[p] = __ldg(bbase + (size_t)(s2 + 2) * sstr + p * 32);
        }
        GSTEP(s2 + 1, b1);
    }

    if (!HEADS) {
#pragma unroll
        for (int am = 0; am < 2; am++)
#pragma unroll
            for (int an = 0; an < AN; an++) {
                size_t r = m0 + wm * 32 + am * 16 + g8;
                int c = n0 + wn * NPW + an * 8 + t4 * 2;
                float bc0 = __ldg(&bias[c]), bc1 = __ldg(&bias[c + 1]);
                float v0 = acc[am][an][0] + bc0;
                float v1 = acc[am][an][1] + bc1;
                v0 = (v0 > 0.0f) ? v0 : expm1f(v0);
                v1 = (v1 > 0.0f) ? v1 : expm1f(v1);
                *(__nv_bfloat162*)(Out + r * (M1) + c) = __floats2bfloat162_rn(v0, v1);
                float v2 = acc[am][an][2] + bc0;
                float v3 = acc[am][an][3] + bc1;
                v2 = (v2 > 0.0f) ? v2 : expm1f(v2);
                v3 = (v3 > 0.0f) ? v3 : expm1f(v3);
                *(__nv_bfloat162*)(Out + (r + 8) * (M1) + c) = __floats2bfloat162_rn(v2, v3);
            }
    } else {
        // ---- tensor-core heads epilogue ----
        __syncthreads();                     // K-loop reads of smA done
        char* ys = smA;                      // 64 x 528B, aliases smA
        for (int u = tid; u < 1024; u += 256) {
            int row = u >> 5, q = u & 31;
            *(uint4*)(smW + row * 528 + q * 16) = *(const uint4*)(g_Whd + row * M2 + q * 8);
        }
#pragma unroll
        for (int am = 0; am < 2; am++)
#pragma unroll
            for (int an = 0; an < AN; an++) {
                int r = wm * 32 + am * 16 + g8;
                int c = wn * NPW + an * 8 + t4 * 2;
                float bc0 = __ldg(&bias[c]), bc1 = __ldg(&bias[c + 1]);
                float v0 = acc[am][an][0] + bc0;
                float v1 = acc[am][an][1] + bc1;
                v0 = (v0 > 0.0f) ? v0 : expm1f(v0);
                v1 = (v1 > 0.0f) ? v1 : expm1f(v1);
                *(__nv_bfloat162*)(ys + r * 528 + c * 2) = __floats2bfloat162_rn(v0, v1);
                float v2 = acc[am][an][2] + bc0;
                float v3 = acc[am][an][3] + bc1;
                v2 = (v2 > 0.0f) ? v2 : expm1f(v2);
                v3 = (v3 > 0.0f) ? v3 : expm1f(v3);
                *(__nv_bfloat162*)(ys + (r + 8) * 528 + c * 2) = __floats2bfloat162_rn(v2, v3);
            }
        __syncthreads();

        if (warp < 4) {
            const uint32_t aH = smem_u32(ys) + (warp * 16 + rowoff) * 528 + kb16;
            const uint32_t smWu = smem_u32(smW);
            const uint32_t bH0 = smWu + rowoff * 528 + kb16;
            const uint32_t bH1 = smWu + (16 + rowoff) * 528 + kb16;

            float ah[4][4];
#pragma unroll
            for (int i = 0; i < 4; i++)
#pragma unroll
                for (int k = 0; k < 4; k++) ah[i][k] = 0.0f;

#pragma unroll
            for (int s = 0; s < 16; s++) {
                uint32_t a0, a1, a2, a3;
                ldsm4(a0, a1, a2, a3, aH + s * 32);
                uint32_t c0r, c1r, c2r, c3r;
                ldsm4(c0r, c1r, c2r, c3r, bH0 + s * 32);
                mma16816(ah[0], a0, a1, a2, a3, c0r, c2r);
                mma16816(ah[1], a0, a1, a2, a3, c1r, c3r);
                ldsm4(c0r, c1r, c2r, c3r, bH1 + s * 32);
                mma16816(ah[2], a0, a1, a2, a3, c0r, c2r);
                mma16816(ah[3], a0, a1, a2, a3, c1r, c3r);
            }

            int r = warp * 16 + g8;
            float Slo = 0.0f, Shi = 0.0f;
#pragma unroll
            for (int an = 0; an < 4; an++)
#pragma unroll
                for (int j = 0; j < 2; j++) {
                    int o = an * 8 + t4 * 2 + j;
                    float vlo = ah[an][j], vhi = ah[an][2 + j];
                    if (o < 12) {
                        float bb = __ldg(&bm[o]);
                        outF[(m0 + r) * 14 + o]     = vlo + bb;
                        outF[(m0 + r + 8) * 14 + o] = vhi + bb;
                    } else if (o < 24) {
                        float bb = __ldg(&bsv[o - 12]);
                        Slo += fminf(fmaxf(vlo + bb, -5.0f), 2.0f);
                        Shi += fminf(fmaxf(vhi + bb, -5.0f), 2.0f);
                    }
                }
            Slo += __shfl_xor_sync(0xffffffffu, Slo, 1);
            Slo += __shfl_xor_sync(0xffffffffu, Slo, 2);
            Shi += __shfl_xor_sync(0xffffffffu, Shi, 1);
            Shi += __shfl_xor_sync(0xffffffffu, Shi, 2);
            if (t4 == 0) {
                outF[(m0 + r) * 14 + 12]     = -Slo - 6.0f * LOG2PI;
                outF[(m0 + r) * 14 + 13]     = Slo + 6.0f + 6.0f * LOG2PI;
                outF[(m0 + r + 8) * 14 + 12] = -Shi - 6.0f * LOG2PI;
                outF[(m0 + r + 8) * 14 + 13] = Shi + 6.0f + 6.0f * LOG2PI;
            }
        }
    }
}

// ---------------- launch ----------------
extern "C" void kernel_launch(void* const* d_in, const int* in_sizes, int n_in,
                              void* d_out, int out_size)
{
    const float *x, *h0, *c0, *W_ih, *W_hh, *b_ih, *b_hh, *ln_g, *ln_b;
    const float *W1, *b1, *W2, *b2, *Wm, *bm, *Ws, *bs;
    const int* done;

    if (in_sizes[1] == TT * BB) {
        // setup_inputs dict order
        x = (const float*)d_in[0];  done = (const int*)d_in[1];
        h0 = (const float*)d_in[2]; c0 = (const float*)d_in[3];
        W_ih = (const float*)d_in[4]; W_hh = (const float*)d_in[5];
        b_ih = (const float*)d_in[6]; b_hh = (const float*)d_in[7];
        ln_g = (const float*)d_in[8]; ln_b = (const float*)d_in[9];
        W1 = (const float*)d_in[10]; b1 = (const float*)d_in[11];
        W2 = (const float*)d_in[12]; b2 = (const float*)d_in[13];
        Wm = (const float*)d_in[14]; bm = (const float*)d_in[15];
        Ws = (const float*)d_in[16]; bs = (const float*)d_in[17];
    } else {
        // reference() signature order
        x = (const float*)d_in[0];
        h0 = (const float*)d_in[1]; c0 = (const float*)d_in[2];
        W_ih = (const float*)d_in[3]; W_hh = (const float*)d_in[4];
        b_ih = (const float*)d_in[5]; b_hh = (const float*)d_in[6];
        ln_g = (const float*)d_in[7]; ln_b = (const float*)d_in[8];
        W1 = (const float*)d_in[9];  b1 = (const float*)d_in[10];
        W2 = (const float*)d_in[11]; b2 = (const float*)d_in[12];
        Wm = (const float*)d_in[13]; bm = (const float*)d_in[14];
        Ws = (const float*)d_in[15]; bs = (const float*)d_in[16];
        done = (const int*)d_in[17];
    }

    float* out = (float*)d_out;

    bf16 *p_hb, *p_y1;
    uint4 *p_W1f, *p_W2f;
    cudaGetSymbolAddress((void**)&p_hb, g_hb);
    cudaGetSymbolAddress((void**)&p_y1, g_y1);
    cudaGetSymbolAddress((void**)&p_W1f, g_W1f);
    cudaGetSymbolAddress((void**)&p_W2f, g_W2f);

    const int SM1 = 64 * (HH + 8) * 2;                 // 33792 (A only)
    const int SM2 = 64 * (M1 + 8) * 2 + 32 * 528;      // 66560 + 16896 = 83456

    cudaFuncSetAttribute(lstm_persist, cudaFuncAttributeMaxDynamicSharedMemorySize, SM_TOTAL);
    cudaFuncSetAttribute(gemm_reg<HH, 128, true, false, 32, 3>,
                         cudaFuncAttributeMaxDynamicSharedMemorySize, SM1);
    cudaFuncSetAttribute(gemm_reg<M1, 256, false, true, 16, 2>,
                         cudaFuncAttributeMaxDynamicSharedMemorySize, SM2);

    // 0. single merged prep (now emits mma-fragment weight layouts)
    prep_all<<<(PREP_TOTAL + 255) / 256, 256>>>(x, W_hh, W_ih, b_ih, b_hh,
                                                W1, W2, Wm, Ws);

    // 1. persistent cluster LSTM (accurate gates)
    lstm_persist<<<128, 256, SM_TOTAL>>>(h0, c0, done);

    // 2. MLP1 (LN fused), B fragments from L2, 3 CTAs/SM
    gemm_reg<HH, 128, true, false, 32, 3><<<dim3(TB / 64, M1 / 128), 256, SM1>>>(
        p_hb, p_W1f, b1, p_y1, ln_g, ln_b, nullptr, nullptr, nullptr);

    // 3. MLP2 + tensor-core heads, B fragments from L2, 2 CTAs/SM
    gemm_reg<M1, 256, false, true, 16, 2><<<dim3(TB / 64, 1), 256, SM2>>>(
        p_y1, p_W2f, b2, nullptr, nullptr, nullptr, bm, bs, out);
}